// round 1
// baseline (speedup 1.0000x reference)
#include <cuda_runtime.h>
#include <cuda_bf16.h>
#include <math.h>

// Problem constants
#define BB 2
#define SS 4096
#define DD 2048
#define HH 16
#define DC 512
#define DKQV 2048
#define DR 1024
#define DCKV 512
#define DOUT 2048
#define DH 128
#define DRH 64
#define MTOK (BB*SS)            // 8192 tokens

__device__ float g_cq [MTOK * DC];     // [8192,512]
__device__ float g_ckv[MTOK * DCKV];   // [8192,512]
__device__ float g_q  [MTOK * DKQV];   // [8192,2048]
__device__ float g_qr [MTOK * DR];     // [8192,1024]
__device__ float g_k  [MTOK * DKQV];
__device__ float g_kr [MTOK * DR];
__device__ float g_v  [MTOK * DKQV];
__device__ float g_o  [MTOK * DKQV];

// ---------------------------------------------------------------------------
// SGEMM: C[M,N] = A[M,K] @ W[K,N] + bias[N]
// BM=BN=128, BK=16, 256 threads, 8x8 micro-tile. M%128==0, N%128==0, K%16==0.
// ---------------------------------------------------------------------------
__global__ __launch_bounds__(256) void sgemm_bias_kernel(
    const float* __restrict__ A, const float* __restrict__ W,
    const float* __restrict__ bias, float* __restrict__ C,
    int M, int N, int K)
{
    const int BM = 128, BN = 128, BK = 16;
    __shared__ float As[BK][BM];
    __shared__ float Bs[BK][BN];

    int bx = blockIdx.x;           // N tile
    int by = blockIdx.y;           // M tile
    int tid = threadIdx.x;
    int tx = tid & 15;             // 0..15 (col group of 8)
    int ty = tid >> 4;             // 0..15 (row group of 8)

    const float* Ab = A + (size_t)by * BM * K;
    const float* Wb = W + (size_t)bx * BN;

    float acc[8][8];
    #pragma unroll
    for (int m = 0; m < 8; m++)
        #pragma unroll
        for (int n = 0; n < 8; n++) acc[m][n] = 0.f;

    for (int k0 = 0; k0 < K; k0 += BK) {
        // Load A tile 128x16 (512 float4, 2 per thread), store transposed
        #pragma unroll
        for (int i = 0; i < 2; i++) {
            int q = tid + i * 256;         // 0..511
            int r = q >> 2;                // 0..127
            int c = (q & 3) << 2;          // 0,4,8,12
            float4 v = *(const float4*)(Ab + (size_t)r * K + k0 + c);
            As[c + 0][r] = v.x;
            As[c + 1][r] = v.y;
            As[c + 2][r] = v.z;
            As[c + 3][r] = v.w;
        }
        // Load B tile 16x128 (512 float4, 2 per thread)
        #pragma unroll
        for (int i = 0; i < 2; i++) {
            int q = tid + i * 256;
            int r = q >> 5;                // 0..15
            int c = (q & 31) << 2;         // 0..124
            float4 v = *(const float4*)(Wb + (size_t)(k0 + r) * N + c);
            *(float4*)&Bs[r][c] = v;
        }
        __syncthreads();

        #pragma unroll
        for (int kk = 0; kk < BK; kk++) {
            float a[8], b[8];
            float4 a0 = *(const float4*)&As[kk][ty * 8];
            float4 a1 = *(const float4*)&As[kk][ty * 8 + 4];
            float4 b0 = *(const float4*)&Bs[kk][tx * 8];
            float4 b1 = *(const float4*)&Bs[kk][tx * 8 + 4];
            a[0]=a0.x; a[1]=a0.y; a[2]=a0.z; a[3]=a0.w;
            a[4]=a1.x; a[5]=a1.y; a[6]=a1.z; a[7]=a1.w;
            b[0]=b0.x; b[1]=b0.y; b[2]=b0.z; b[3]=b0.w;
            b[4]=b1.x; b[5]=b1.y; b[6]=b1.z; b[7]=b1.w;
            #pragma unroll
            for (int m = 0; m < 8; m++)
                #pragma unroll
                for (int n = 0; n < 8; n++)
                    acc[m][n] = fmaf(a[m], b[n], acc[m][n]);
        }
        __syncthreads();
    }

    // Epilogue: add bias, store
    int col0 = bx * BN + tx * 8;
    float bv[8];
    #pragma unroll
    for (int n = 0; n < 8; n++) bv[n] = bias[col0 + n];

    #pragma unroll
    for (int m = 0; m < 8; m++) {
        int row = by * BM + ty * 8 + m;
        float* Crow = C + (size_t)row * N + col0;
        float4 v0, v1;
        v0.x = acc[m][0] + bv[0]; v0.y = acc[m][1] + bv[1];
        v0.z = acc[m][2] + bv[2]; v0.w = acc[m][3] + bv[3];
        v1.x = acc[m][4] + bv[4]; v1.y = acc[m][5] + bv[5];
        v1.z = acc[m][6] + bv[6]; v1.w = acc[m][7] + bv[7];
        *(float4*)(Crow)     = v0;
        *(float4*)(Crow + 4) = v1;
    }
}

// ---------------------------------------------------------------------------
// Per-token attention: rope(q_r), rope(k_r), concat, 16x16 scores, softmax
// over heads, attn @ v. One block of 256 threads per token.
// ---------------------------------------------------------------------------
#define QK_STRIDE 193   // 192 + 1 pad: stride%32==1 -> conflict-free k-row reads

__global__ __launch_bounds__(256) void attn_kernel(
    const float* __restrict__ qbuf, const float* __restrict__ qrbuf,
    const float* __restrict__ kbuf, const float* __restrict__ krbuf,
    const float* __restrict__ vbuf, float* __restrict__ obuf)
{
    const float SCALER = 1.0f / sqrtf((float)(DH + DRH));   // 1/sqrt(192)
    const float LOG1E4 = 9.210340371976184f;                 // ln(10000)

    int t = blockIdx.x;            // token index 0..8191
    int s = t & (SS - 1);          // position in sequence
    int tid = threadIdx.x;

    __shared__ float qf[HH][QK_STRIDE];
    __shared__ float kf[HH][QK_STRIDE];
    __shared__ float vv[HH][DH];
    __shared__ float sc[HH][HH];
    __shared__ float at[HH][HH];

    const float* qp  = qbuf  + (size_t)t * DKQV;
    const float* kp  = kbuf  + (size_t)t * DKQV;
    const float* vp  = vbuf  + (size_t)t * DKQV;
    const float* qrp = qrbuf + (size_t)t * DR;
    const float* krp = krbuf + (size_t)t * DR;

    // base parts
    for (int idx = tid; idx < HH * DH; idx += 256) {
        int h = idx >> 7, d = idx & 127;
        qf[h][d] = qp[idx];
        kf[h][d] = kp[idx];
        vv[h][d] = vp[idx];
    }
    // rope parts: 16 heads x 32 rotation pairs = 512
    for (int idx = tid; idx < HH * 32; idx += 256) {
        int h = idx >> 5, j = idx & 31;
        float invf = expf(-LOG1E4 * ((float)(2 * j) / 64.0f));
        float ang = (float)s * invf;
        float sj, cj;
        sincosf(ang, &sj, &cj);
        float x1q = qrp[h * DRH + j], x2q = qrp[h * DRH + j + 32];
        qf[h][DH + j]      = x1q * cj - x2q * sj;
        qf[h][DH + j + 32] = x2q * cj + x1q * sj;
        float x1k = krp[h * DRH + j], x2k = krp[h * DRH + j + 32];
        kf[h][DH + j]      = x1k * cj - x2k * sj;
        kf[h][DH + j + 32] = x2k * cj + x1k * sj;
    }
    __syncthreads();

    // scores: thread (i,j) does 192-elem dot
    {
        int i = tid >> 4, j = tid & 15;
        float dsum = 0.f;
        #pragma unroll 8
        for (int d = 0; d < DH + DRH; d++)
            dsum = fmaf(qf[i][d], kf[j][d], dsum);
        sc[i][j] = dsum * SCALER;
    }
    __syncthreads();

    // softmax over j (16 threads, one row each)
    if (tid < HH) {
        float mx = -1e30f;
        #pragma unroll
        for (int j = 0; j < HH; j++) mx = fmaxf(mx, sc[tid][j]);
        float e[HH], sum = 0.f;
        #pragma unroll
        for (int j = 0; j < HH; j++) { e[j] = expf(sc[tid][j] - mx); sum += e[j]; }
        float inv = 1.0f / sum;
        #pragma unroll
        for (int j = 0; j < HH; j++) at[tid][j] = e[j] * inv;
    }
    __syncthreads();

    // out = attn @ v  (2048 outputs, 8 per thread)
    float* op = obuf + (size_t)t * DKQV;
    for (int idx = tid; idx < HH * DH; idx += 256) {
        int i = idx >> 7, d = idx & 127;
        float acc = 0.f;
        #pragma unroll
        for (int j = 0; j < HH; j++)
            acc = fmaf(at[i][j], vv[j][d], acc);
        op[idx] = acc;
    }
}

// ---------------------------------------------------------------------------
// Launch
// ---------------------------------------------------------------------------
static void launch_gemm(const float* A, const float* W, const float* b,
                        float* C, int M, int N, int K)
{
    dim3 grid(N / 128, M / 128);
    sgemm_bias_kernel<<<grid, 256>>>(A, W, b, C, M, N, K);
}

extern "C" void kernel_launch(void* const* d_in, const int* in_sizes, int n_in,
                              void* d_out, int out_size)
{
    const float* h_t  = (const float*)d_in[0];
    const float* Wc   = (const float*)d_in[1];
    const float* bc   = (const float*)d_in[2];
    const float* Wcq  = (const float*)d_in[3];
    const float* bcq  = (const float*)d_in[4];
    const float* Wqr  = (const float*)d_in[5];
    const float* bqr  = (const float*)d_in[6];
    const float* Wckv = (const float*)d_in[7];
    const float* bckv = (const float*)d_in[8];
    const float* Wck  = (const float*)d_in[9];
    const float* bck  = (const float*)d_in[10];
    const float* Wkr  = (const float*)d_in[11];
    const float* bkr  = (const float*)d_in[12];
    const float* Wv   = (const float*)d_in[13];
    const float* bv   = (const float*)d_in[14];
    const float* Wo   = (const float*)d_in[15];
    const float* bo   = (const float*)d_in[16];
    float* out = (float*)d_out;

    float *cq, *ckv, *q, *qr, *k, *kr, *v, *o;
    cudaGetSymbolAddress((void**)&cq,  g_cq);
    cudaGetSymbolAddress((void**)&ckv, g_ckv);
    cudaGetSymbolAddress((void**)&q,   g_q);
    cudaGetSymbolAddress((void**)&qr,  g_qr);
    cudaGetSymbolAddress((void**)&k,   g_k);
    cudaGetSymbolAddress((void**)&kr,  g_kr);
    cudaGetSymbolAddress((void**)&v,   g_v);
    cudaGetSymbolAddress((void**)&o,   g_o);

    // Stage 1: from h_t
    launch_gemm(h_t, Wc,   bc,   cq,  MTOK, DC,   DD);   // cq
    launch_gemm(h_t, Wckv, bckv, ckv, MTOK, DCKV, DD);   // ckv
    launch_gemm(h_t, Wkr,  bkr,  kr,  MTOK, DR,   DD);   // kr (pre-rope)

    // Stage 2: projections
    launch_gemm(cq,  Wcq, bcq, q,  MTOK, DKQV, DC);      // q base
    launch_gemm(cq,  Wqr, bqr, qr, MTOK, DR,   DC);      // qr (pre-rope)
    launch_gemm(ckv, Wck, bck, k,  MTOK, DKQV, DCKV);    // k base
    launch_gemm(ckv, Wv,  bv,  v,  MTOK, DKQV, DCKV);    // v

    // Stage 3: per-token attention (rope fused)
    attn_kernel<<<MTOK, 256>>>(q, qr, k, kr, v, o);

    // Stage 4: output projection
    launch_gemm(o, Wo, bo, out, MTOK, DOUT, DKQV);
}

// round 5
// speedup vs baseline: 2.5219x; 2.5219x over previous
#include <cuda_runtime.h>
#include <cuda_bf16.h>
#include <math.h>
#include <stdint.h>

// ---------------------------------------------------------------------------
// Problem constants
// ---------------------------------------------------------------------------
#define BB 2
#define SS 4096
#define HH 16
#define DKQV 2048
#define DH 128
#define DRH 64
#define MTOK (BB*SS)            // 8192 tokens

// ---------------------------------------------------------------------------
// Device scratch
// ---------------------------------------------------------------------------
__device__ float g_s1 [MTOK * 2048];   // cq | ckv | kr
__device__ float g_s2 [MTOK * 3072];   // q | qr
__device__ float g_s3 [MTOK * 4096];   // k | v
__device__ float g_ob [MTOK * 2048];   // attention out
// transposed bf16 hi/lo weights [N,K]
__device__ __nv_bfloat16 g_w1h[2048 * 2048], g_w1l[2048 * 2048];
__device__ __nv_bfloat16 g_w2h[3072 * 512],  g_w2l[3072 * 512];
__device__ __nv_bfloat16 g_w3h[4096 * 512],  g_w3l[4096 * 512];
__device__ __nv_bfloat16 g_w4h[2048 * 2048], g_w4l[2048 * 2048];
__device__ float g_b1 [2048];
__device__ float g_b2 [3072];
__device__ float g_b3 [4096];

// ---------------------------------------------------------------------------
// GEMM config: CTA 128x128, BK=32, 128 threads (4 warps, each 64x64)
// A smem fp32 [128][36]; B smem bf16x2 u32 [128][20] (hi and lo)
// ---------------------------------------------------------------------------
#define BM 128
#define BN 128
#define BK 32
#define ASTRIDE 36
#define BSTRIDE 20
#define A_TILE_B (128 * ASTRIDE * 4)          // 18432
#define B_TILE_B (128 * BSTRIDE * 4)          // 10240
#define STAGE_B (A_TILE_B + 2 * B_TILE_B)     // 38912
#define SMEM_BYTES (2 * STAGE_B)              // 77824

__device__ __forceinline__ uint32_t smem_u32(const void* p) {
    uint32_t a;
    asm("{ .reg .u64 t; cvta.to.shared.u64 t, %1; cvt.u32.u64 %0, t; }"
        : "=r"(a) : "l"(p));
    return a;
}
__device__ __forceinline__ void cp_async16(uint32_t dst, const void* src) {
    asm volatile("cp.async.cg.shared.global [%0], [%1], 16;"
                 :: "r"(dst), "l"(src) : "memory");
}
__device__ __forceinline__ void cp_commit() {
    asm volatile("cp.async.commit_group;" ::: "memory");
}
__device__ __forceinline__ void cp_wait1() {
    asm volatile("cp.async.wait_group 1;" ::: "memory");
}

__device__ __forceinline__ void mma_bf16(float c[4], uint32_t a0, uint32_t a1,
                                         uint32_t a2, uint32_t a3,
                                         uint32_t b0, uint32_t b1) {
    asm volatile(
        "mma.sync.aligned.m16n8k16.row.col.f32.bf16.bf16.f32 "
        "{%0,%1,%2,%3}, {%4,%5,%6,%7}, {%8,%9}, {%0,%1,%2,%3};"
        : "+f"(c[0]), "+f"(c[1]), "+f"(c[2]), "+f"(c[3])
        : "r"(a0), "r"(a1), "r"(a2), "r"(a3), "r"(b0), "r"(b1));
}

// Split two fp32 into packed bf16x2 hi + lo (lo = x - float(hi))
__device__ __forceinline__ void split_pair(float x0, float x1,
                                           uint32_t& h, uint32_t& l) {
    asm("cvt.rn.bf16x2.f32 %0, %1, %2;" : "=r"(h) : "f"(x1), "f"(x0));
    float h0 = __uint_as_float(h << 16);
    float h1 = __uint_as_float(h & 0xFFFF0000u);
    float l0 = x0 - h0, l1 = x1 - h1;
    asm("cvt.rn.bf16x2.f32 %0, %1, %2;" : "=r"(l) : "f"(l1), "f"(l0));
}

// A: 128x32 fp32 tile (row-major, ld) -> smem [128][36]
__device__ __forceinline__ void tileA_async(const float* __restrict__ g, int ld,
                                            uint32_t sbase, int tid) {
#pragma unroll
    for (int j = 0; j < 8; j++) {
        int idx = tid + j * 128;
        int r = idx >> 3, c = idx & 7;
        cp_async16(sbase + (uint32_t)(r * ASTRIDE + c * 4) * 4,
                   g + (size_t)r * ld + c * 4);
    }
}
// B: 128x32 bf16 tile ([N,K] row-major, ld=K) -> smem u32 [128][20]
__device__ __forceinline__ void tileB_async(const __nv_bfloat16* __restrict__ g,
                                            int ld, uint32_t sbase, int tid) {
#pragma unroll
    for (int j = 0; j < 4; j++) {
        int idx = tid + j * 128;
        int r = idx >> 2, c = idx & 3;     // c: 16B chunk = 8 bf16
        cp_async16(sbase + (uint32_t)(r * BSTRIDE + c * 4) * 4,
                   g + (size_t)r * ld + c * 8);
    }
}

// ---------------------------------------------------------------------------
// bf16x3 GEMM: C[M,N] = A[M,K](fp32,lda) @ (Bh+Bl)[N,K]^T + bias
// ---------------------------------------------------------------------------
__global__ void __launch_bounds__(128) gemm_bf16x3_kernel(
    const float* __restrict__ A, int lda,
    const __nv_bfloat16* __restrict__ Bh,
    const __nv_bfloat16* __restrict__ Bl,
    const float* __restrict__ bias,
    float* __restrict__ C,
    int M, int N, int K)
{
    extern __shared__ float smem[];
    const uint32_t sb = smem_u32(smem);
    const int tid = threadIdx.x;
    const int wid = tid >> 5;
    const int lane = tid & 31;
    const int g = lane >> 2;
    const int t = lane & 3;
    const int wm = (wid & 1) * 64;
    const int wn = (wid >> 1) * 64;

    const int m0 = blockIdx.y * BM;
    const int n0 = blockIdx.x * BN;
    const float* Abase = A + (size_t)m0 * lda;
    const __nv_bfloat16* BhBase = Bh + (size_t)n0 * K;
    const __nv_bfloat16* BlBase = Bl + (size_t)n0 * K;

    const uint32_t stA[2]  = { sb,              sb + STAGE_B };
    const uint32_t stBh[2] = { sb + A_TILE_B,   sb + STAGE_B + A_TILE_B };
    const uint32_t stBl[2] = { sb + A_TILE_B + B_TILE_B,
                               sb + STAGE_B + A_TILE_B + B_TILE_B };

    float acc[4][8][4];
#pragma unroll
    for (int mf = 0; mf < 4; mf++)
#pragma unroll
        for (int nf = 0; nf < 8; nf++)
#pragma unroll
            for (int r = 0; r < 4; r++) acc[mf][nf][r] = 0.f;

    const int NC = K / BK;

    tileA_async(Abase, lda, stA[0], tid);
    tileB_async(BhBase, K, stBh[0], tid);
    tileB_async(BlBase, K, stBl[0], tid);
    cp_commit();
    tileA_async(Abase + BK, lda, stA[1], tid);
    tileB_async(BhBase + BK, K, stBh[1], tid);
    tileB_async(BlBase + BK, K, stBl[1], tid);
    cp_commit();

    for (int i = 0; i < NC; i++) {
        cp_wait1();
        __syncthreads();
        const int s = i & 1;
        const float* As = smem + (stA[s] - sb) / 4;
        const uint32_t* BsH = (const uint32_t*)smem + (stBh[s] - sb) / 4;
        const uint32_t* BsL = (const uint32_t*)smem + (stBl[s] - sb) / 4;

#pragma unroll
        for (int ks = 0; ks < 2; ks++) {       // two k16 steps
            const int kc = ks * 16;
            uint32_t ah[4][4], al[4][4];
#pragma unroll
            for (int mf = 0; mf < 4; mf++) {
                const float* ap  = As + (wm + mf * 16 + g) * ASTRIDE + kc + 2 * t;
                const float* ap8 = ap + 8 * ASTRIDE;
                split_pair(ap [0], ap [1], ah[mf][0], al[mf][0]);
                split_pair(ap8[0], ap8[1], ah[mf][1], al[mf][1]);
                split_pair(ap [8], ap [9], ah[mf][2], al[mf][2]);
                split_pair(ap8[8], ap8[9], ah[mf][3], al[mf][3]);
            }
            uint32_t bh[8][2], bl[8][2];
#pragma unroll
            for (int nf = 0; nf < 8; nf++) {
                const int rb = (wn + nf * 8 + g) * BSTRIDE + ks * 8 + t;
                bh[nf][0] = BsH[rb];
                bh[nf][1] = BsH[rb + 4];
                bl[nf][0] = BsL[rb];
                bl[nf][1] = BsL[rb + 4];
            }
#pragma unroll
            for (int mf = 0; mf < 4; mf++)
#pragma unroll
                for (int nf = 0; nf < 8; nf++) {
                    mma_bf16(acc[mf][nf], ah[mf][0], ah[mf][1], ah[mf][2],
                             ah[mf][3], bh[nf][0], bh[nf][1]);
                    mma_bf16(acc[mf][nf], ah[mf][0], ah[mf][1], ah[mf][2],
                             ah[mf][3], bl[nf][0], bl[nf][1]);
                    mma_bf16(acc[mf][nf], al[mf][0], al[mf][1], al[mf][2],
                             al[mf][3], bh[nf][0], bh[nf][1]);
                }
        }
        __syncthreads();
        if (i + 2 < NC) {
            const int k0 = (i + 2) * BK;
            tileA_async(Abase + k0, lda, stA[s], tid);
            tileB_async(BhBase + k0, K, stBh[s], tid);
            tileB_async(BlBase + k0, K, stBl[s], tid);
        }
        cp_commit();
    }

    // Epilogue
#pragma unroll
    for (int mf = 0; mf < 4; mf++) {
        const int row0 = m0 + wm + mf * 16 + g;
#pragma unroll
        for (int nf = 0; nf < 8; nf++) {
            const int col = n0 + wn + nf * 8 + 2 * t;
            const float b0 = bias[col], b1 = bias[col + 1];
            float2 v0 = { acc[mf][nf][0] + b0, acc[mf][nf][1] + b1 };
            float2 v1 = { acc[mf][nf][2] + b0, acc[mf][nf][3] + b1 };
            *(float2*)(C + (size_t)row0 * N + col) = v0;
            *(float2*)(C + (size_t)(row0 + 8) * N + col) = v1;
        }
    }
}

// ---------------------------------------------------------------------------
// Transpose + bf16 hi/lo split: src[rows,cols] fp32 -> hi/lo[cols,rows] bf16
// ---------------------------------------------------------------------------
__global__ void transpose_split(const float* __restrict__ src,
                                __nv_bfloat16* __restrict__ hi,
                                __nv_bfloat16* __restrict__ lo,
                                int rows, int cols)
{
    __shared__ float tile[32][33];
    const int c0 = blockIdx.x * 32, r0 = blockIdx.y * 32;
    for (int i = threadIdx.y; i < 32; i += 8)
        tile[i][threadIdx.x] = src[(size_t)(r0 + i) * cols + c0 + threadIdx.x];
    __syncthreads();
    for (int i = threadIdx.y; i < 32; i += 8) {
        float x = tile[threadIdx.x][i];
        __nv_bfloat16 h = __float2bfloat16_rn(x);
        __nv_bfloat16 l = __float2bfloat16_rn(x - __bfloat162float(h));
        size_t o = (size_t)(c0 + i) * rows + r0 + threadIdx.x;
        hi[o] = h;
        lo[o] = l;
    }
}

__global__ void copyf(const float* __restrict__ s, float* __restrict__ d, int n)
{
    int i = blockIdx.x * 256 + threadIdx.x;
    if (i < n) d[i] = s[i];
}

// ---------------------------------------------------------------------------
// Per-token attention (rope fused). 256 threads / token.
// ---------------------------------------------------------------------------
#define QK_STRIDE 193

__global__ void __launch_bounds__(256) attn_kernel(
    const float* __restrict__ s1, const float* __restrict__ s2,
    const float* __restrict__ s3, float* __restrict__ obuf)
{
    const float SCALER = 1.0f / sqrtf((float)(DH + DRH));
    const float LOG1E4 = 9.210340371976184f;

    int tk = blockIdx.x;
    int s = tk & (SS - 1);
    int tid = threadIdx.x;

    __shared__ float qf[HH][QK_STRIDE];
    __shared__ float kf[HH][QK_STRIDE];
    __shared__ float vv[HH][DH];
    __shared__ float sc[HH][HH];
    __shared__ float at[HH][HH];

    const float* qp  = s2 + (size_t)tk * 3072;
    const float* qrp = qp + 2048;
    const float* kp  = s3 + (size_t)tk * 4096;
    const float* vp  = kp + 2048;
    const float* krp = s1 + (size_t)tk * 2048 + 1024;

    for (int idx = tid; idx < HH * DH; idx += 256) {
        int h = idx >> 7, d = idx & 127;
        qf[h][d] = qp[idx];
        kf[h][d] = kp[idx];
        vv[h][d] = vp[idx];
    }
    for (int idx = tid; idx < HH * 32; idx += 256) {
        int h = idx >> 5, j = idx & 31;
        float invf = expf(-LOG1E4 * ((float)(2 * j) / 64.0f));
        float ang = (float)s * invf;
        float sj, cj;
        sincosf(ang, &sj, &cj);
        float x1q = qrp[h * DRH + j], x2q = qrp[h * DRH + j + 32];
        qf[h][DH + j]      = x1q * cj - x2q * sj;
        qf[h][DH + j + 32] = x2q * cj + x1q * sj;
        float x1k = krp[h * DRH + j], x2k = krp[h * DRH + j + 32];
        kf[h][DH + j]      = x1k * cj - x2k * sj;
        kf[h][DH + j + 32] = x2k * cj + x1k * sj;
    }
    __syncthreads();

    {
        int i = tid >> 4, j = tid & 15;
        float dsum = 0.f;
#pragma unroll 8
        for (int d = 0; d < DH + DRH; d++)
            dsum = fmaf(qf[i][d], kf[j][d], dsum);
        sc[i][j] = dsum * SCALER;
    }
    __syncthreads();

    if (tid < HH) {
        float mx = -1e30f;
#pragma unroll
        for (int j = 0; j < HH; j++) mx = fmaxf(mx, sc[tid][j]);
        float e[HH], sum = 0.f;
#pragma unroll
        for (int j = 0; j < HH; j++) { e[j] = expf(sc[tid][j] - mx); sum += e[j]; }
        float inv = 1.0f / sum;
#pragma unroll
        for (int j = 0; j < HH; j++) at[tid][j] = e[j] * inv;
    }
    __syncthreads();

    float* op = obuf + (size_t)tk * DKQV;
    for (int idx = tid; idx < HH * DH; idx += 256) {
        int i = idx >> 7, d = idx & 127;
        float acc = 0.f;
#pragma unroll
        for (int j = 0; j < HH; j++)
            acc = fmaf(at[i][j], vv[j][d], acc);
        op[idx] = acc;
    }
}

// ---------------------------------------------------------------------------
// Launch
// ---------------------------------------------------------------------------
static void launch_gemm(const float* A, int lda, const __nv_bfloat16* Bh,
                        const __nv_bfloat16* Bl, const float* bias,
                        float* C, int M, int N, int K)
{
    cudaFuncSetAttribute(gemm_bf16x3_kernel,
                         cudaFuncAttributeMaxDynamicSharedMemorySize, SMEM_BYTES);
    dim3 grid(N / BN, M / BM);
    gemm_bf16x3_kernel<<<grid, 128, SMEM_BYTES>>>(A, lda, Bh, Bl, bias, C, M, N, K);
}

static void launch_tsplit(const float* src, __nv_bfloat16* hi, __nv_bfloat16* lo,
                          int rows, int cols)
{
    dim3 grid(cols / 32, rows / 32), blk(32, 8);
    transpose_split<<<grid, blk>>>(src, hi, lo, rows, cols);
}

static void launch_copy(const float* s, float* d, int n)
{
    copyf<<<(n + 255) / 256, 256>>>(s, d, n);
}

extern "C" void kernel_launch(void* const* d_in, const int* in_sizes, int n_in,
                              void* d_out, int out_size)
{
    const float* h_t  = (const float*)d_in[0];
    const float* Wc   = (const float*)d_in[1];
    const float* bc   = (const float*)d_in[2];
    const float* Wcq  = (const float*)d_in[3];
    const float* bcq  = (const float*)d_in[4];
    const float* Wqr  = (const float*)d_in[5];
    const float* bqr  = (const float*)d_in[6];
    const float* Wckv = (const float*)d_in[7];
    const float* bckv = (const float*)d_in[8];
    const float* Wck  = (const float*)d_in[9];
    const float* bck  = (const float*)d_in[10];
    const float* Wkr  = (const float*)d_in[11];
    const float* bkr  = (const float*)d_in[12];
    const float* Wv   = (const float*)d_in[13];
    const float* bv   = (const float*)d_in[14];
    const float* Wo   = (const float*)d_in[15];
    const float* bo   = (const float*)d_in[16];
    float* out = (float*)d_out;

    float *s1, *s2, *s3, *ob, *b1, *b2, *b3;
    __nv_bfloat16 *w1h, *w1l, *w2h, *w2l, *w3h, *w3l, *w4h, *w4l;
    cudaGetSymbolAddress((void**)&s1,  g_s1);
    cudaGetSymbolAddress((void**)&s2,  g_s2);
    cudaGetSymbolAddress((void**)&s3,  g_s3);
    cudaGetSymbolAddress((void**)&ob,  g_ob);
    cudaGetSymbolAddress((void**)&w1h, g_w1h);
    cudaGetSymbolAddress((void**)&w1l, g_w1l);
    cudaGetSymbolAddress((void**)&w2h, g_w2h);
    cudaGetSymbolAddress((void**)&w2l, g_w2l);
    cudaGetSymbolAddress((void**)&w3h, g_w3h);
    cudaGetSymbolAddress((void**)&w3l, g_w3l);
    cudaGetSymbolAddress((void**)&w4h, g_w4h);
    cudaGetSymbolAddress((void**)&w4l, g_w4l);
    cudaGetSymbolAddress((void**)&b1,  g_b1);
    cudaGetSymbolAddress((void**)&b2,  g_b2);
    cudaGetSymbolAddress((void**)&b3,  g_b3);

    // Pack: transpose + hi/lo split of all weights into [N,K] bf16
    launch_tsplit(Wc,   w1h + (size_t)0    * 2048, w1l + (size_t)0    * 2048, 2048, 512);
    launch_tsplit(Wckv, w1h + (size_t)512  * 2048, w1l + (size_t)512  * 2048, 2048, 512);
    launch_tsplit(Wkr,  w1h + (size_t)1024 * 2048, w1l + (size_t)1024 * 2048, 2048, 1024);
    launch_tsplit(Wcq,  w2h + (size_t)0    * 512,  w2l + (size_t)0    * 512,  512, 2048);
    launch_tsplit(Wqr,  w2h + (size_t)2048 * 512,  w2l + (size_t)2048 * 512,  512, 1024);
    launch_tsplit(Wck,  w3h + (size_t)0    * 512,  w3l + (size_t)0    * 512,  512, 2048);
    launch_tsplit(Wv,   w3h + (size_t)2048 * 512,  w3l + (size_t)2048 * 512,  512, 2048);
    launch_tsplit(Wo,   w4h, w4l, 2048, 2048);
    launch_copy(bc,   b1,        512);
    launch_copy(bckv, b1 + 512,  512);
    launch_copy(bkr,  b1 + 1024, 1024);
    launch_copy(bcq,  b2,        2048);
    launch_copy(bqr,  b2 + 2048, 1024);
    launch_copy(bck,  b3,        2048);
    launch_copy(bv,   b3 + 2048, 2048);

    // G1: h_t -> (cq|ckv|kr)
    launch_gemm(h_t, 2048, w1h, w1l, b1, s1, MTOK, 2048, 2048);
    // G2: cq -> (q|qr)
    launch_gemm(s1, 2048, w2h, w2l, b2, s2, MTOK, 3072, 512);
    // G3: ckv -> (k|v)
    launch_gemm(s1 + 512, 2048, w3h, w3l, b3, s3, MTOK, 4096, 512);
    // attention
    attn_kernel<<<MTOK, 256>>>(s1, s2, s3, ob);
    // G4: o -> out
    launch_gemm(ob, 2048, w4h, w4l, bo, out, MTOK, 2048, 2048);
}